// round 6
// baseline (speedup 1.0000x reference)
#include <cuda_runtime.h>
#include <cstdint>

#define TN 2048
#define BN 256
#define DN 40
#define HN 128
#define CN 35
#define TDN (TN * DN)
#define NCTA 128

// ---------------------------------------------------------------------------
// Persistent device scratch.
__device__ __align__(16) float g_xT[TDN * BN];     // x transposed: [t*D + d][b]
__device__ __align__(16) float g_h0[2][HN * BN];   // layer0 h double buffer, [k][b]
__device__ __align__(16) float g_h1[2][HN * BN];   // layer1 h double buffer, [k][b]

struct alignas(128) BarSlot { unsigned v; };
__device__ BarSlot g_cnt[5];                       // 4 groups + 1 full
__device__ volatile BarSlot g_phz[5];              // phases (monotonic, never reset)

// ---------------------------------------------------------------------------
union F2U { float2 f; unsigned long long u; };
__device__ __forceinline__ void ffma2(float2& acc, float2 a, float2 b) {
    F2U ua, ub, uc;
    ua.f = a; ub.f = b; uc.f = acc;
    asm("fma.rn.f32x2 %0, %1, %2, %0;" : "+l"(uc.u) : "l"(ua.u), "l"(ub.u));
    acc = uc.f;
}
__device__ __forceinline__ float sigf(float x)  { return 1.0f / (1.0f + __expf(-x)); }
__device__ __forceinline__ float tanhx(float x) {
    x = fminf(fmaxf(x, -15.f), 15.f);
    float e = __expf(2.f * x);
    return (e - 1.f) / (e + 1.f);
}

// Grid barrier over `n` CTAs sharing slot `g`. Phase is monotonic across the
// whole run (incl. graph replays), so no re-init is ever needed.
__device__ __forceinline__ void gbar(int g, unsigned n) {
    __syncthreads();
    if (threadIdx.x == 0) {
        unsigned ph = g_phz[g].v;
        __threadfence();
        if (atomicAdd(&g_cnt[g].v, 1u) == n - 1u) {
            g_cnt[g].v = 0u;
            __threadfence();
            g_phz[g].v = ph + 1u;
        } else {
            while (g_phz[g].v == ph) { }
            __threadfence();
        }
    }
    __syncthreads();
}

// ---------------------------------------------------------------------------
// SMEM plan (~128.3 KB dynamic).
struct SmemLayout {
    float2 wB[8][4][HN];   // W_ih rows, dup {w,w}   (32 KB)
    float2 wA[8][4][HN];   // W_hh rows, dup {w,w}   (32 KB)
    float2 sbd[8][4];      // bias dup
    float  sin1[HN * 64];  // staged input 1 [k][64] (32 KB)
    float  sin2[HN * 64];  // staged input 2 [k][64] (32 KB)
};
#define SMEM_BYTES ((int)sizeof(SmemLayout))

struct LstmArgs {
    const float *x;
    const int   *length;
    const float *Wih0, *Whh0, *bih0, *bhh0;
    const float *Wih1, *Whh1, *bih1, *bhh1;
    const float *lng, *lnb, *fcw, *fcb;
    float       *out;
};

// Stage `rows` x 64 floats from src (row stride BN, column offset bbase).
__device__ __forceinline__ void stage_tile(float* dst, const float* src,
                                           int rows, int bbase, int tid) {
    int total = rows * 16;  // float4s
    for (int i = tid; i < total; i += 128) {
        int r = i >> 4, j = (i & 15) << 2;
        float4 v = __ldcg((const float4*)(src + (size_t)r * BN + bbase + j));
        *(float4*)(dst + r * 64 + j) = v;
    }
}

// ---------------------------------------------------------------------------
// Per-layer step loop. CTA = 8 units x 64 batch, 4 warps; warp = 2 units.
// Thread: units (lu0, lu0+1), batch rows (b0, b0+1) within its bblock.
template <int LAYER>
__device__ void run_layer(const LstmArgs& a, SmemLayout* sm,
                          int u0, int bbase, int grp)
{
    constexpr int K1 = LAYER ? HN : DN;
    const int tid = threadIdx.x;
    const int lu0 = (tid >> 5) * 2;       // warp -> local unit pair
    const int b0  = 2 * (tid & 31);
    const int gu0 = u0 + lu0;

    const float* Wih = LAYER ? a.Wih1 : a.Wih0;
    const float* Whh = LAYER ? a.Whh1 : a.Whh0;
    const float* bih = LAYER ? a.bih1 : a.bih0;
    const float* bhh = LAYER ? a.bhh1 : a.bhh0;

    // ---- stage duplicated weights + bias (once) ----
    for (int i = tid; i < 32 * K1; i += 128) {
        int r = i / K1, k = i - r * K1;
        int uu = r >> 2, g = r & 3;
        float w = Wih[(size_t)(g * HN + u0 + uu) * K1 + k];
        sm->wB[uu][g][k] = make_float2(w, w);
    }
    for (int i = tid; i < 32 * HN; i += 128) {
        int r = i >> 7, k = i & 127;
        int uu = r >> 2, g = r & 3;
        float w = Whh[(size_t)(g * HN + u0 + uu) * HN + k];
        sm->wA[uu][g][k] = make_float2(w, w);
    }
    if (tid < 32) {
        int uu = tid >> 2, g = tid & 3;
        float b = bih[g * HN + u0 + uu] + bhh[g * HN + u0 + uu];
        sm->sbd[uu][g] = make_float2(b, b);
    }

    const int len0 = a.length[bbase + b0];
    const int len1 = a.length[bbase + b0 + 1];

    float cA0 = 0.f, cB0 = 0.f, hA0 = 0.f, hB0 = 0.f;
    float cA1 = 0.f, cB1 = 0.f, hA1 = 0.f, hB1 = 0.f;
    __syncthreads();

#pragma unroll 1
    for (int it = 0; it <= TN; it++) {
        const int  t      = LAYER ? it - 1 : it;
        const bool active = LAYER ? (it >= 1) : (it < TN);
        if (active) {
            const float* in1  = LAYER ? g_h0[t & 1]
                                      : (g_xT + (size_t)t * DN * BN);
            const float* in2  = LAYER ? g_h1[(t + 1) & 1] : g_h0[(t + 1) & 1];
            float*       hout = LAYER ? g_h1[t & 1]       : g_h0[t & 1];

            stage_tile(sm->sin1, in1, K1, bbase, tid);
            stage_tile(sm->sin2, in2, HN, bbase, tid);
            __syncthreads();

            float2 acc0[4], acc1[4];
#pragma unroll
            for (int g = 0; g < 4; g++) {
                acc0[g] = sm->sbd[lu0][g];
                acc1[g] = sm->sbd[lu0 + 1][g];
            }

            // ---- part 1: W_ih * input ----
            {
                const float* sv = sm->sin1 + b0;
#pragma unroll 2
                for (int k4 = 0; k4 < K1; k4 += 4) {
                    float2 v0 = *(const float2*)(sv + (k4 + 0) * 64);
                    float2 v1 = *(const float2*)(sv + (k4 + 1) * 64);
                    float2 v2 = *(const float2*)(sv + (k4 + 2) * 64);
                    float2 v3 = *(const float2*)(sv + (k4 + 3) * 64);
#pragma unroll
                    for (int g = 0; g < 4; g++) {
                        float4 wa = *(const float4*)&sm->wB[lu0][g][k4];
                        float4 wb = *(const float4*)&sm->wB[lu0][g][k4 + 2];
                        ffma2(acc0[g], make_float2(wa.x, wa.y), v0);
                        ffma2(acc0[g], make_float2(wa.z, wa.w), v1);
                        ffma2(acc0[g], make_float2(wb.x, wb.y), v2);
                        ffma2(acc0[g], make_float2(wb.z, wb.w), v3);
                    }
#pragma unroll
                    for (int g = 0; g < 4; g++) {
                        float4 wa = *(const float4*)&sm->wB[lu0 + 1][g][k4];
                        float4 wb = *(const float4*)&sm->wB[lu0 + 1][g][k4 + 2];
                        ffma2(acc1[g], make_float2(wa.x, wa.y), v0);
                        ffma2(acc1[g], make_float2(wa.z, wa.w), v1);
                        ffma2(acc1[g], make_float2(wb.x, wb.y), v2);
                        ffma2(acc1[g], make_float2(wb.z, wb.w), v3);
                    }
                }
            }
            // ---- part 2: W_hh * h_prev ----
            {
                const float* sv = sm->sin2 + b0;
#pragma unroll 2
                for (int k4 = 0; k4 < HN; k4 += 4) {
                    float2 v0 = *(const float2*)(sv + (k4 + 0) * 64);
                    float2 v1 = *(const float2*)(sv + (k4 + 1) * 64);
                    float2 v2 = *(const float2*)(sv + (k4 + 2) * 64);
                    float2 v3 = *(const float2*)(sv + (k4 + 3) * 64);
#pragma unroll
                    for (int g = 0; g < 4; g++) {
                        float4 wa = *(const float4*)&sm->wA[lu0][g][k4];
                        float4 wb = *(const float4*)&sm->wA[lu0][g][k4 + 2];
                        ffma2(acc0[g], make_float2(wa.x, wa.y), v0);
                        ffma2(acc0[g], make_float2(wa.z, wa.w), v1);
                        ffma2(acc0[g], make_float2(wb.x, wb.y), v2);
                        ffma2(acc0[g], make_float2(wb.z, wb.w), v3);
                    }
#pragma unroll
                    for (int g = 0; g < 4; g++) {
                        float4 wa = *(const float4*)&sm->wA[lu0 + 1][g][k4];
                        float4 wb = *(const float4*)&sm->wA[lu0 + 1][g][k4 + 2];
                        ffma2(acc1[g], make_float2(wa.x, wa.y), v0);
                        ffma2(acc1[g], make_float2(wa.z, wa.w), v1);
                        ffma2(acc1[g], make_float2(wb.x, wb.y), v2);
                        ffma2(acc1[g], make_float2(wb.z, wb.w), v3);
                    }
                }
            }

            // ---- gates -> state (freeze for t >= length) ----
            {
                float i_ = sigf(acc0[0].x), f_ = sigf(acc0[1].x);
                float g_ = tanhx(acc0[2].x), o_ = sigf(acc0[3].x);
                float cn = f_ * cA0 + i_ * g_;
                float hn = o_ * tanhx(cn);
                if (t < len0) { cA0 = cn; hA0 = hn; }
            }
            {
                float i_ = sigf(acc0[0].y), f_ = sigf(acc0[1].y);
                float g_ = tanhx(acc0[2].y), o_ = sigf(acc0[3].y);
                float cn = f_ * cB0 + i_ * g_;
                float hn = o_ * tanhx(cn);
                if (t < len1) { cB0 = cn; hB0 = hn; }
            }
            {
                float i_ = sigf(acc1[0].x), f_ = sigf(acc1[1].x);
                float g_ = tanhx(acc1[2].x), o_ = sigf(acc1[3].x);
                float cn = f_ * cA1 + i_ * g_;
                float hn = o_ * tanhx(cn);
                if (t < len0) { cA1 = cn; hA1 = hn; }
            }
            {
                float i_ = sigf(acc1[0].y), f_ = sigf(acc1[1].y);
                float g_ = tanhx(acc1[2].y), o_ = sigf(acc1[3].y);
                float cn = f_ * cB1 + i_ * g_;
                float hn = o_ * tanhx(cn);
                if (t < len1) { cB1 = cn; hB1 = hn; }
            }
            __stcg((float2*)&hout[(size_t)gu0 * BN + bbase + b0],
                   make_float2(hA0, hB0));
            __stcg((float2*)&hout[(size_t)(gu0 + 1) * BN + bbase + b0],
                   make_float2(hA1, hB1));
        }
        gbar(grp, 32);
    }
}

// ---------------------------------------------------------------------------
// Single persistent kernel: transpose + zero, 2049 steps, LN+FC head.
__global__ void __launch_bounds__(128, 1) lstm_kernel(LstmArgs a) {
    extern __shared__ char smem_raw[];
    SmemLayout* sm = (SmemLayout*)smem_raw;
    const int bid = blockIdx.x;
    const int tid = threadIdx.x;

    // ---- phase 0: transpose x into g_xT + zero h buffers ----
    {
        float (*tile)[33] = (float(*)[33])sm->sin1;  // 32x33 scratch
        const int tx = tid & 31, ty = tid >> 5;      // 32 x 4
        const int ntile = (TDN / 32) * (BN / 32);    // 20480
        for (int tl = bid; tl < ntile; tl += NCTA) {
            int tdBase = (tl % (TDN / 32)) * 32;
            int bBase  = (tl / (TDN / 32)) * 32;
#pragma unroll
            for (int j = 0; j < 8; j++)
                tile[ty + j * 4][tx] =
                    a.x[(size_t)(bBase + ty + j * 4) * TDN + tdBase + tx];
            __syncthreads();
#pragma unroll
            for (int j = 0; j < 8; j++)
                g_xT[(size_t)(tdBase + ty + j * 4) * BN + bBase + tx] =
                    tile[tx][ty + j * 4];
            __syncthreads();
        }
        for (int i = bid * 128 + tid; i < HN * BN; i += NCTA * 128) {
            g_h0[0][i] = 0.f; g_h0[1][i] = 0.f;
            g_h1[0][i] = 0.f; g_h1[1][i] = 0.f;
        }
    }
    gbar(4, NCTA);   // full barrier

    // ---- phase 1: step loop (layer-split, grouped barriers) ----
    const int blk   = bid & 63;
    const int u0    = (blk >> 2) * 8;
    const int grp   = blk & 3;
    const int bbase = grp * 64;
    if (bid < 64) run_layer<0>(a, sm, u0, bbase, grp);
    else          run_layer<1>(a, sm, u0, bbase, grp);

    // ---- phase 2: LN + FC head (2 batch rows per CTA, group-local) ----
    {
        float* hv  = sm->sin1;        // reuse SMEM
        float* red = sm->sin1 + 160;
        const int idx = ((bid >> 6) << 4) | ((bid >> 2) & 15);  // 0..31 in group
        const int brow = bbase + idx * 2;

        for (int rep = 0; rep < 2; rep++) {
            int b = brow + rep;
            float v = g_h1[(TN - 1) & 1][(size_t)tid * BN + b];

            float s = v;
#pragma unroll
            for (int o = 16; o; o >>= 1) s += __shfl_xor_sync(0xffffffffu, s, o);
            if ((tid & 31) == 0) red[tid >> 5] = s;
            __syncthreads();
            float mu = (red[0] + red[1] + red[2] + red[3]) * (1.0f / HN);

            float d = v - mu;
            float q = d * d;
#pragma unroll
            for (int o = 16; o; o >>= 1) q += __shfl_xor_sync(0xffffffffu, q, o);
            __syncthreads();
            if ((tid & 31) == 0) red[tid >> 5] = q;
            __syncthreads();
            float var = (red[0] + red[1] + red[2] + red[3]) * (1.0f / HN);

            hv[tid] = d * rsqrtf(var + 1e-5f) * a.lng[tid] + a.lnb[tid];
            __syncthreads();

            if (tid < CN) {
                float acc = a.fcb[tid];
#pragma unroll 4
                for (int h = 0; h < HN; h++)
                    acc = fmaf(hv[h], a.fcw[tid * HN + h], acc);
                a.out[b * CN + tid] = acc;
            }
            __syncthreads();
        }
    }
}

// ---------------------------------------------------------------------------
extern "C" void kernel_launch(void* const* d_in, const int* in_sizes, int n_in,
                              void* d_out, int out_size)
{
    LstmArgs a;
    a.x      = (const float*)d_in[0];
    a.length = (const int*)  d_in[1];
    a.Wih0 = (const float*)d_in[2];
    a.Whh0 = (const float*)d_in[3];
    a.bih0 = (const float*)d_in[4];
    a.bhh0 = (const float*)d_in[5];
    a.Wih1 = (const float*)d_in[6];
    a.Whh1 = (const float*)d_in[7];
    a.bih1 = (const float*)d_in[8];
    a.bhh1 = (const float*)d_in[9];
    a.lng  = (const float*)d_in[10];
    a.lnb  = (const float*)d_in[11];
    a.fcw  = (const float*)d_in[12];
    a.fcb  = (const float*)d_in[13];
    a.out  = (float*)d_out;

    static bool attr_done = false;
    if (!attr_done) {
        cudaFuncSetAttribute(lstm_kernel,
                             cudaFuncAttributeMaxDynamicSharedMemorySize,
                             SMEM_BYTES);
        attr_done = true;
    }

    lstm_kernel<<<NCTA, 128, SMEM_BYTES>>>(a);
}

// round 7
// speedup vs baseline: 1.1948x; 1.1948x over previous
#include <cuda_runtime.h>
#include <cstdint>

#define TN 2048
#define BN 256
#define DN 40
#define HN 128
#define CN 35
#define TDN (TN * DN)
#define NCTA 128
#define NTHR 256

// ---------------------------------------------------------------------------
// Persistent device scratch.
__device__ __align__(16) float g_xT[TDN * BN];     // x transposed: [t*D + d][b]
__device__ __align__(16) float g_h0[2][HN * BN];   // layer0 h double buffer, [k][b]
__device__ __align__(16) float g_h1[2][HN * BN];   // layer1 h double buffer, [k][b]

struct alignas(128) BarSlot { unsigned v; };
__device__ BarSlot g_cnt[5];                       // 4 groups + 1 full
__device__ volatile BarSlot g_phz[5];              // monotonic phases

// ---------------------------------------------------------------------------
union F2U { float2 f; unsigned long long u; };
__device__ __forceinline__ void ffma2(float2& acc, float2 a, float2 b) {
    F2U ua, ub, uc;
    ua.f = a; ub.f = b; uc.f = acc;
    asm("fma.rn.f32x2 %0, %1, %2, %0;" : "+l"(uc.u) : "l"(ua.u), "l"(ub.u));
    acc = uc.f;
}
__device__ __forceinline__ float sigf(float x)  { return 1.0f / (1.0f + __expf(-x)); }
__device__ __forceinline__ float tanhx(float x) {
    x = fminf(fmaxf(x, -15.f), 15.f);
    float e = __expf(2.f * x);
    return (e - 1.f) / (e + 1.f);
}

__device__ __forceinline__ void gbar(int g, unsigned n) {
    __syncthreads();
    if (threadIdx.x == 0) {
        unsigned ph = g_phz[g].v;
        __threadfence();
        if (atomicAdd(&g_cnt[g].v, 1u) == n - 1u) {
            g_cnt[g].v = 0u;
            __threadfence();
            g_phz[g].v = ph + 1u;
        } else {
            while (g_phz[g].v == ph) { }
            __threadfence();
        }
    }
    __syncthreads();
}

// ---------------------------------------------------------------------------
// SMEM (~136.3 KB dynamic).
struct SmemLayout {
    float2 wB[8][4][HN];     // W_ih rows, dup {w,w}   (32 KB)
    float2 wA[8][4][HN];     // W_hh rows, dup {w,w}   (32 KB)
    float2 sbd[8][4];        // bias dup
    float  sin1[HN * 64];    // staged input 1 [k][64] (32 KB)
    float  sin2[HN * 64];    // staged input 2 [k][64] (32 KB)
    float2 red2[128][8];     // k-split partial accs    (8 KB)
};
#define SMEM_BYTES ((int)sizeof(SmemLayout))

struct LstmArgs {
    const float *x;
    const int   *length;
    const float *Wih0, *Whh0, *bih0, *bhh0;
    const float *Wih1, *Whh1, *bih1, *bhh1;
    const float *lng, *lnb, *fcw, *fcb;
    float       *out;
};

// Stage `rows` x 64 floats from src (row stride BN, column offset bbase).
__device__ __forceinline__ void stage_tile(float* dst, const float* src,
                                           int rows, int bbase, int tid) {
    int total = rows * 16;  // float4s
    for (int i = tid; i < total; i += NTHR) {
        int r = i >> 4, j = (i & 15) << 2;
        float4 v = __ldcg((const float4*)(src + (size_t)r * BN + bbase + j));
        *(float4*)(dst + r * 64 + j) = v;
    }
}

// MAC over k range [kbeg, kend) for one unit-pair against staged inputs.
__device__ __forceinline__ void mac_range(
    float2 acc0[4], float2 acc1[4],
    const float2 (*w)[4][HN], int lu0,
    const float* sv, int kbeg, int kend)
{
#pragma unroll 2
    for (int k4 = kbeg; k4 < kend; k4 += 4) {
        float2 v0 = *(const float2*)(sv + (k4 + 0) * 64);
        float2 v1 = *(const float2*)(sv + (k4 + 1) * 64);
        float2 v2 = *(const float2*)(sv + (k4 + 2) * 64);
        float2 v3 = *(const float2*)(sv + (k4 + 3) * 64);
#pragma unroll
        for (int g = 0; g < 4; g++) {
            float4 wa = *(const float4*)&w[lu0][g][k4];
            float4 wb = *(const float4*)&w[lu0][g][k4 + 2];
            ffma2(acc0[g], make_float2(wa.x, wa.y), v0);
            ffma2(acc0[g], make_float2(wa.z, wa.w), v1);
            ffma2(acc0[g], make_float2(wb.x, wb.y), v2);
            ffma2(acc0[g], make_float2(wb.z, wb.w), v3);
        }
#pragma unroll
        for (int g = 0; g < 4; g++) {
            float4 wa = *(const float4*)&w[lu0 + 1][g][k4];
            float4 wb = *(const float4*)&w[lu0 + 1][g][k4 + 2];
            ffma2(acc1[g], make_float2(wa.x, wa.y), v0);
            ffma2(acc1[g], make_float2(wa.z, wa.w), v1);
            ffma2(acc1[g], make_float2(wb.x, wb.y), v2);
            ffma2(acc1[g], make_float2(wb.z, wb.w), v3);
        }
    }
}

// ---------------------------------------------------------------------------
// Per-layer step loop. CTA = 8 units x 64 batch, 256 threads (8 warps).
// Warp (wp, ks): wp -> unit pair (2wp, 2wp+1); ks -> k-half. Thread: batch
// rows (b0, b0+1). ks=1 warps compute partial MACs and hand off via SMEM;
// ks=0 warps reduce + activations + h store.
template <int LAYER>
__device__ void run_layer(const LstmArgs& a, SmemLayout* sm,
                          int u0, int bbase, int grp)
{
    constexpr int K1  = LAYER ? HN : DN;
    constexpr int KH1 = K1 / 2;
    const int tid  = threadIdx.x;
    const int wid  = tid >> 5;
    const int lane = tid & 31;
    const int ks   = wid & 1;
    const int wp   = wid >> 1;
    const int lu0  = wp * 2;
    const int b0   = 2 * lane;
    const int gu0  = u0 + lu0;
    const int ridx = wp * 32 + lane;

    const float* Wih = LAYER ? a.Wih1 : a.Wih0;
    const float* Whh = LAYER ? a.Whh1 : a.Whh0;
    const float* bih = LAYER ? a.bih1 : a.bih0;
    const float* bhh = LAYER ? a.bhh1 : a.bhh0;

    // ---- stage duplicated weights + bias (once) ----
    for (int i = tid; i < 32 * K1; i += NTHR) {
        int r = i / K1, k = i - r * K1;
        int uu = r >> 2, g = r & 3;
        float w = Wih[(size_t)(g * HN + u0 + uu) * K1 + k];
        sm->wB[uu][g][k] = make_float2(w, w);
    }
    for (int i = tid; i < 32 * HN; i += NTHR) {
        int r = i >> 7, k = i & 127;
        int uu = r >> 2, g = r & 3;
        float w = Whh[(size_t)(g * HN + u0 + uu) * HN + k];
        sm->wA[uu][g][k] = make_float2(w, w);
    }
    if (tid < 32) {
        int uu = tid >> 2, g = tid & 3;
        float b = bih[g * HN + u0 + uu] + bhh[g * HN + u0 + uu];
        sm->sbd[uu][g] = make_float2(b, b);
    }

    const int len0 = a.length[bbase + b0];
    const int len1 = a.length[bbase + b0 + 1];

    float cA0 = 0.f, cB0 = 0.f, hA0 = 0.f, hB0 = 0.f;
    float cA1 = 0.f, cB1 = 0.f, hA1 = 0.f, hB1 = 0.f;
    __syncthreads();

#pragma unroll 1
    for (int it = 0; it <= TN; it++) {
        const int  t      = LAYER ? it - 1 : it;
        const bool active = LAYER ? (it >= 1) : (it < TN);
        if (active) {
            const float* in1  = LAYER ? g_h0[t & 1]
                                      : (g_xT + (size_t)t * DN * BN);
            const float* in2  = LAYER ? g_h1[(t + 1) & 1] : g_h0[(t + 1) & 1];
            float*       hout = LAYER ? g_h1[t & 1]       : g_h0[t & 1];

            stage_tile(sm->sin1, in1, K1, bbase, tid);
            stage_tile(sm->sin2, in2, HN, bbase, tid);
            __syncthreads();

            float2 acc0[4], acc1[4];
            if (ks == 0) {
#pragma unroll
                for (int g = 0; g < 4; g++) {
                    acc0[g] = sm->sbd[lu0][g];
                    acc1[g] = sm->sbd[lu0 + 1][g];
                }
            } else {
#pragma unroll
                for (int g = 0; g < 4; g++) {
                    acc0[g] = make_float2(0.f, 0.f);
                    acc1[g] = make_float2(0.f, 0.f);
                }
            }

            mac_range(acc0, acc1, sm->wB, lu0, sm->sin1 + b0,
                      ks * KH1, ks * KH1 + KH1);
            mac_range(acc0, acc1, sm->wA, lu0, sm->sin2 + b0,
                      ks * 64, ks * 64 + 64);

            // ---- k-split handoff ----
            if (ks == 1) {
#pragma unroll
                for (int g = 0; g < 4; g++) {
                    sm->red2[ridx][g]     = acc0[g];
                    sm->red2[ridx][g + 4] = acc1[g];
                }
            }
            __syncthreads();
            if (ks == 0) {
#pragma unroll
                for (int g = 0; g < 4; g++) {
                    float2 p0 = sm->red2[ridx][g];
                    float2 p1 = sm->red2[ridx][g + 4];
                    acc0[g].x += p0.x; acc0[g].y += p0.y;
                    acc1[g].x += p1.x; acc1[g].y += p1.y;
                }
                // gates -> state (freeze for t >= length)
                {
                    float i_ = sigf(acc0[0].x), f_ = sigf(acc0[1].x);
                    float g_ = tanhx(acc0[2].x), o_ = sigf(acc0[3].x);
                    float cn = f_ * cA0 + i_ * g_;
                    float hn = o_ * tanhx(cn);
                    if (t < len0) { cA0 = cn; hA0 = hn; }
                }
                {
                    float i_ = sigf(acc0[0].y), f_ = sigf(acc0[1].y);
                    float g_ = tanhx(acc0[2].y), o_ = sigf(acc0[3].y);
                    float cn = f_ * cB0 + i_ * g_;
                    float hn = o_ * tanhx(cn);
                    if (t < len1) { cB0 = cn; hB0 = hn; }
                }
                {
                    float i_ = sigf(acc1[0].x), f_ = sigf(acc1[1].x);
                    float g_ = tanhx(acc1[2].x), o_ = sigf(acc1[3].x);
                    float cn = f_ * cA1 + i_ * g_;
                    float hn = o_ * tanhx(cn);
                    if (t < len0) { cA1 = cn; hA1 = hn; }
                }
                {
                    float i_ = sigf(acc1[0].y), f_ = sigf(acc1[1].y);
                    float g_ = tanhx(acc1[2].y), o_ = sigf(acc1[3].y);
                    float cn = f_ * cB1 + i_ * g_;
                    float hn = o_ * tanhx(cn);
                    if (t < len1) { cB1 = cn; hB1 = hn; }
                }
                __stcg((float2*)&hout[(size_t)gu0 * BN + bbase + b0],
                       make_float2(hA0, hB0));
                __stcg((float2*)&hout[(size_t)(gu0 + 1) * BN + bbase + b0],
                       make_float2(hA1, hB1));
            }
        }
        gbar(grp, 32);
    }
}

// ---------------------------------------------------------------------------
// Single persistent kernel: transpose + zero, 2049 steps, LN+FC head.
__global__ void __launch_bounds__(NTHR, 1) lstm_kernel(LstmArgs a) {
    extern __shared__ char smem_raw[];
    SmemLayout* sm = (SmemLayout*)smem_raw;
    const int bid = blockIdx.x;
    const int tid = threadIdx.x;

    // ---- phase 0: transpose x into g_xT + zero h buffers ----
    {
        float (*tile)[33] = (float(*)[33])sm->sin1;  // 32x33 scratch
        const int tx = tid & 31, ty = tid >> 5;      // 32 x 8
        const int ntile = (TDN / 32) * (BN / 32);    // 20480
        for (int tl = bid; tl < ntile; tl += NCTA) {
            int tdBase = (tl % (TDN / 32)) * 32;
            int bBase  = (tl / (TDN / 32)) * 32;
#pragma unroll
            for (int j = 0; j < 4; j++)
                tile[ty + j * 8][tx] =
                    a.x[(size_t)(bBase + ty + j * 8) * TDN + tdBase + tx];
            __syncthreads();
#pragma unroll
            for (int j = 0; j < 4; j++)
                g_xT[(size_t)(tdBase + ty + j * 8) * BN + bBase + tx] =
                    tile[tx][ty + j * 8];
            __syncthreads();
        }
        for (int i = bid * NTHR + tid; i < HN * BN; i += NCTA * NTHR) {
            g_h0[0][i] = 0.f; g_h0[1][i] = 0.f;
            g_h1[0][i] = 0.f; g_h1[1][i] = 0.f;
        }
    }
    gbar(4, NCTA);   // full barrier

    // ---- phase 1: step loop (layer-split, grouped barriers) ----
    const int blk   = bid & 63;
    const int u0    = (blk >> 2) * 8;
    const int grp   = blk & 3;
    const int bbase = grp * 64;
    if (bid < 64) run_layer<0>(a, sm, u0, bbase, grp);
    else          run_layer<1>(a, sm, u0, bbase, grp);

    // ---- phase 2: LN + FC head (2 batch rows per CTA) ----
    {
        float* hv  = sm->sin1;
        float* red = sm->sin1 + 160;
        const int idx = ((bid >> 6) << 4) | ((bid >> 2) & 15);  // 0..31 in group
        const int brow = bbase + idx * 2;

        for (int rep = 0; rep < 2; rep++) {
            int b = brow + rep;
            float v = (tid < HN)
                ? __ldcg(&g_h1[(TN - 1) & 1][(size_t)tid * BN + b]) : 0.f;

            float s = v;
#pragma unroll
            for (int o = 16; o; o >>= 1) s += __shfl_xor_sync(0xffffffffu, s, o);
            if ((tid & 31) == 0 && tid < HN) red[tid >> 5] = s;
            __syncthreads();
            float mu = (red[0] + red[1] + red[2] + red[3]) * (1.0f / HN);

            float d = (tid < HN) ? (v - mu) : 0.f;
            float q = d * d;
#pragma unroll
            for (int o = 16; o; o >>= 1) q += __shfl_xor_sync(0xffffffffu, q, o);
            __syncthreads();
            if ((tid & 31) == 0 && tid < HN) red[tid >> 5] = q;
            __syncthreads();
            float var = (red[0] + red[1] + red[2] + red[3]) * (1.0f / HN);

            if (tid < HN)
                hv[tid] = d * rsqrtf(var + 1e-5f) * a.lng[tid] + a.lnb[tid];
            __syncthreads();

            if (tid < CN) {
                float acc = a.fcb[tid];
#pragma unroll 4
                for (int h = 0; h < HN; h++)
                    acc = fmaf(hv[h], a.fcw[tid * HN + h], acc);
                a.out[b * CN + tid] = acc;
            }
            __syncthreads();
        }
    }
}

// ---------------------------------------------------------------------------
extern "C" void kernel_launch(void* const* d_in, const int* in_sizes, int n_in,
                              void* d_out, int out_size)
{
    LstmArgs a;
    a.x      = (const float*)d_in[0];
    a.length = (const int*)  d_in[1];
    a.Wih0 = (const float*)d_in[2];
    a.Whh0 = (const float*)d_in[3];
    a.bih0 = (const float*)d_in[4];
    a.bhh0 = (const float*)d_in[5];
    a.Wih1 = (const float*)d_in[6];
    a.Whh1 = (const float*)d_in[7];
    a.bih1 = (const float*)d_in[8];
    a.bhh1 = (const float*)d_in[9];
    a.lng  = (const float*)d_in[10];
    a.lnb  = (const float*)d_in[11];
    a.fcw  = (const float*)d_in[12];
    a.fcb  = (const float*)d_in[13];
    a.out  = (float*)d_out;

    static bool attr_done = false;
    if (!attr_done) {
        cudaFuncSetAttribute(lstm_kernel,
                             cudaFuncAttributeMaxDynamicSharedMemorySize,
                             SMEM_BYTES);
        attr_done = true;
    }

    lstm_kernel<<<NCTA, NTHR, SMEM_BYTES>>>(a);
}